// round 16
// baseline (speedup 1.0000x reference)
#include <cuda_runtime.h>
#include <math.h>
#include <float.h>

// Problem constants
#define BATCH 4
#define N0    4096
#define C0    72
#define G1    2048
#define C1    144
#define G2    1024
#define C2OUT 288
#define KNB   24

typedef unsigned long long u64;

// ---------------- scratch (static device globals; no allocation) ----------------
__device__ float  g_featsT0[BATCH * N0 * C0];
__device__ int    g_fi1[BATCH * G1];
__device__ float  g_lc1[BATCH * G1 * 3];
__device__ int    g_ki1[BATCH * G1 * KNB];
__device__ float  g_pooled1[BATCH * G1 * C1];
__device__ float  g_featsT1[BATCH * G1 * C1];
__device__ int    g_fi2[BATCH * G2];
__device__ float  g_lc2[BATCH * G2 * 3];
__device__ int    g_ki2[BATCH * G2 * KNB];
__device__ float  g_pooled2[BATCH * G2 * C2OUT];
__device__ double g_acc[4];                       // sumX, sumX2, sumZ, sumZ2
__device__ double g_bnacc1[C2OUT];
__device__ double g_bnacc2[C2OUT];
__device__ float  g_bnscale[C2OUT];
__device__ float  g_bnshift[C2OUT];
__device__ float  g_sc1[24];                      // stage1 1000/dim_embed
__device__ float  g_sc2[48];                      // stage2 1000/dim_embed

// ---------------- packed f32x2 helpers ----------------
__device__ __forceinline__ u64 pk2(float lo, float hi) {
    u64 r; asm("mov.b64 %0, {%1, %2};" : "=l"(r) : "f"(lo), "f"(hi)); return r;
}
__device__ __forceinline__ void upk2(u64 v, float& lo, float& hi) {
    asm("mov.b64 {%0, %1}, %2;" : "=f"(lo), "=f"(hi) : "l"(v));
}
__device__ __forceinline__ u64 add2(u64 a, u64 b) {
    u64 r; asm("add.rn.f32x2 %0, %1, %2;" : "=l"(r) : "l"(a), "l"(b)); return r;
}
__device__ __forceinline__ u64 mul2(u64 a, u64 b) {
    u64 r; asm("mul.rn.f32x2 %0, %1, %2;" : "=l"(r) : "l"(a), "l"(b)); return r;
}
__device__ __forceinline__ u64 fma2(u64 a, u64 b, u64 c) {
    u64 r; asm("fma.rn.f32x2 %0, %1, %2, %3;" : "=l"(r) : "l"(a), "l"(b), "l"(c)); return r;
}

// ---------------- fast sincos: Cody-Waite mod 2pi + MUFU ----------------
__device__ __forceinline__ void fsincos(float x, float& s, float& c) {
    float q = rintf(x * 0.15915494309189535f);
    float r = fmaf(q, -6.2831855f, x);
    r = fmaf(q, 1.7484556e-7f, r);
    __sincosf(r, &s, &c);
}

// ---------------- init: zero accumulators, build dim_embed tables ----------------
__global__ void initk() {
    int t = threadIdx.x;
    if (t < 4)  g_acc[t] = 0.0;
    if (t < 24) g_sc1[t] = (float)(1000.0 / pow(100.0, (double)t / 24.0));
    if (t < 48) g_sc2[t] = (float)(1000.0 / pow(100.0, (double)t / 48.0));
    for (int i = t; i < C2OUT; i += blockDim.x) { g_bnacc1[i] = 0.0; g_bnacc2[i] = 0.0; }
}

// ---------------- transpose [B][C][N] -> [B][N][C] (single launch) ----------------
__global__ void transpose_full(const float* __restrict__ x, float* __restrict__ o) {
    size_t tot = (size_t)BATCH * C0 * N0;
    for (size_t i = (size_t)blockIdx.x * blockDim.x + threadIdx.x; i < tot;
         i += (size_t)gridDim.x * blockDim.x) {
        size_t b   = i / ((size_t)C0 * N0);
        size_t rem = i - b * (size_t)C0 * N0;
        size_t c   = rem / N0;
        size_t n   = rem - c * N0;
        o[(b * N0 + n) * C0 + c] = x[i];
    }
}

// ---------------- furthest point sampling ----------------
// One block per batch, 1024 threads, PPT contiguous points per thread.
// Cross-warp winner via ONE packed 64-bit smem atomicMax per warp:
//   key = (dist_bits << 32) | (0xFFFFFFFF - index)
// -> max dist, tie -> lowest index (global first-max, matching jnp.argmax).
// Post-barrier: single 64-bit LDS + 3 broadcast coord LDS. Triple-buffered
// slots; slot (it+1)%3 is reset at iteration top (two barriers separate the
// reset from both the previous reads and the next atomics).
template<int PPT>
__global__ void __launch_bounds__(1024) fps_kernel(const float* __restrict__ pts,
                                                   int m,
                                                   int* __restrict__ fi,
                                                   float* __restrict__ lc) {
    const int T = 1024;
    const int N = T * PPT;
    const int P2 = PPT / 2;
    extern __shared__ float spts[];              // N*3 floats
    __shared__ u64 swin[3];
    int b = blockIdx.x;
    const float* P = pts + (size_t)b * N * 3;
    int tid = threadIdx.x, lane = tid & 31;
    int base = tid * PPT;

    {   // coalesced smem tile
        const float4* P4 = (const float4*)P;
        float4* S4 = (float4*)spts;
#pragma unroll
        for (int i = tid; i < N * 3 / 4; i += T) S4[i] = P4[i];
    }
    if (tid < 3) swin[tid] = 0ull;

    u64 X[P2], Y[P2], Z[P2];
    float dist[PPT];
#pragma unroll
    for (int j = 0; j < P2; j++) {
        int n0 = (base + 2 * j) * 3;
        X[j] = pk2(P[n0 + 0], P[n0 + 3]);
        Y[j] = pk2(P[n0 + 1], P[n0 + 4]);
        Z[j] = pk2(P[n0 + 2], P[n0 + 5]);
        dist[2 * j] = 1e10f; dist[2 * j + 1] = 1e10f;
    }
    __syncthreads();

    float cx = spts[0], cy = spts[1], cz = spts[2];
    unsigned curidx = 0;
    int buf = 0, rbuf = 1;                       // rbuf = (buf+1)%3

    for (int it = 0; it < m; it++) {
        if (tid == 0) {
            fi[b * m + it] = (int)curidx;
            lc[(size_t)(b * m + it) * 3 + 0] = cx;
            lc[(size_t)(b * m + it) * 3 + 1] = cy;
            lc[(size_t)(b * m + it) * 3 + 2] = cz;
            swin[rbuf] = 0ull;                   // reset slot for iteration it+1
        }
        u64 mcx = pk2(-cx, -cx), mcy = pk2(-cy, -cy), mcz = pk2(-cz, -cz);
        float mx0 = -1.0f, mx1 = -1.0f;
#pragma unroll
        for (int j = 0; j < P2; j++) {
            u64 dx = add2(X[j], mcx);
            u64 dy = add2(Y[j], mcy);
            u64 dz = add2(Z[j], mcz);
            u64 t  = mul2(dz, dz);
            t = fma2(dy, dy, t);
            t = fma2(dx, dx, t);               // == fmaf(dx,dx,fmaf(dy,dy,dz*dz)) per half
            float t0, t1; upk2(t, t0, t1);
            float nd0 = fminf(dist[2 * j],     t0);
            float nd1 = fminf(dist[2 * j + 1], t1);
            dist[2 * j] = nd0;
            dist[2 * j + 1] = nd1;
            mx0 = fmaxf(mx0, nd0);
            mx1 = fmaxf(mx1, nd1);
        }
        float mx = fmaxf(mx0, mx1);
        unsigned dbits = __float_as_uint(mx);            // >=0 -> monotone as uint
        unsigned md  = __reduce_max_sync(0xffffffffu, dbits);
        unsigned bal = __ballot_sync(0xffffffffu, dbits == md);
        if (lane == __ffs(bal) - 1) {                    // lowest lane = lowest index
            int loc = 0;
#pragma unroll
            for (int j = PPT - 1; j >= 0; j--)           // smallest j with dist==mx
                if (dist[j] == mx) loc = j;
            u64 key = ((u64)md << 32) | (u64)(0xFFFFFFFFu - (unsigned)(base + loc));
            atomicMax(&swin[buf], key);
        }
        __syncthreads();
        u64 w = swin[buf];
        unsigned bn = 0xFFFFFFFFu - (unsigned)(w & 0xFFFFFFFFull);
        cx = spts[bn * 3 + 0];
        cy = spts[bn * 3 + 1];
        cz = spts[bn * 3 + 2];
        curidx = bn;
        buf  = (buf  == 2) ? 0 : buf + 1;
        rbuf = (rbuf == 2) ? 0 : rbuf + 1;
    }
}

// ---------------- kNN (smem tile, two-pass threshold) + fused global-std ----------------
template<int N, int C>
__global__ void __launch_bounds__(512) knn_std_kernel(
    const float* __restrict__ pts, const float* __restrict__ ctr,
    const float* __restrict__ featsT, const int* __restrict__ fi,
    int* __restrict__ ki, int G)
{
    extern __shared__ float dynsmem[];
    float* spts = dynsmem;                       // N*3 floats
    int*   skout = (int*)(dynsmem + N * 3);      // 16*KNB ints
    float* sacc  = (float*)(skout + 16 * KNB);   // 4 floats

    int tid = threadIdx.x, lane = tid & 31, warp = tid >> 5;
    int gw = blockIdx.x * 16 + warp;
    int b = gw / G;                              // block-uniform (G % 16 == 0)
    const float* P = pts + (size_t)b * N * 3;

    {   // coalesced tile load
        const float4* P4 = (const float4*)P;
        float4* S4 = (float4*)spts;
        for (int i = tid; i < N * 3 / 4; i += 512) S4[i] = P4[i];
    }
    if (tid < 4) sacc[tid] = 0.0f;
    __syncthreads();

    float cx = ctr[(size_t)gw * 3 + 0];
    float cy = ctr[(size_t)gw * 3 + 1];
    float cz = ctr[(size_t)gw * 3 + 2];

    // ---- pass 1: per-lane min -> tau bound ----
    float mn = FLT_MAX;
    for (int n = lane; n < N; n += 32) {
        float dx = spts[n * 3 + 0] - cx;
        float dy = spts[n * 3 + 1] - cy;
        float dz = spts[n * 3 + 2] - cz;
        mn = fminf(mn, fmaf(dx, dx, fmaf(dy, dy, dz * dz)));
    }
    float v = mn;
#pragma unroll
    for (int k = 2; k <= 32; k <<= 1) {
#pragma unroll
        for (int j = k >> 1; j > 0; j >>= 1) {
            float o = __shfl_xor_sync(0xffffffffu, v, j);
            bool dirUp   = ((lane & k) == 0);
            bool takeLow = ((lane & j) == 0);
            v = (dirUp == takeLow) ? fminf(v, o) : fmaxf(v, o);
        }
    }
    float tau = __shfl_sync(0xffffffffu, v, KNB - 1);   // 24th smallest lane-min

    // ---- pass 2: thresholded insertion ----
    float kd[KNB]; int kix[KNB];
#pragma unroll
    for (int i = 0; i < KNB; i++) { kd[i] = FLT_MAX; kix[i] = 0x7fffffff; }
    float wd = FLT_MAX; int wi = 0x7fffffff;

    for (int n = lane; n < N; n += 32) {
        float dx = spts[n * 3 + 0] - cx;
        float dy = spts[n * 3 + 1] - cy;
        float dz = spts[n * 3 + 2] - cz;
        float d  = fmaf(dx, dx, fmaf(dy, dy, dz * dz));
        if (d > tau) continue;                   // cannot be in global top-24
        if (d < wd || (d == wd && n < wi)) {
            int i = KNB - 1;
            while (i > 0 && (kd[i - 1] > d || (kd[i - 1] == d && kix[i - 1] > n))) {
                kd[i] = kd[i - 1]; kix[i] = kix[i - 1]; i--;
            }
            kd[i] = d; kix[i] = n;
            wd = kd[KNB - 1]; wi = kix[KNB - 1];
        }
    }

    // warp merge: 24 rounds of lexicographic min extraction
    int my_k = 0;
    int pos = 0;
    for (int r = 0; r < KNB; r++) {
        float vv = (pos < KNB) ? kd[pos]  : FLT_MAX;
        int   id = (pos < KNB) ? kix[pos] : 0x7fffffff;
        float bv = vv; int bi = id;
#pragma unroll
        for (int off = 16; off; off >>= 1) {
            float ov = __shfl_xor_sync(0xffffffffu, bv, off);
            int   oi = __shfl_xor_sync(0xffffffffu, bi, off);
            if (ov < bv || (ov == bv && oi < bi)) { bv = ov; bi = oi; }
        }
        if (id == bi && vv == bv) pos++;
        if (lane == r) my_k = bi;
    }
    if (lane < KNB) {
        ki[(size_t)gw * KNB + lane] = my_k;
        skout[warp * KNB + lane] = my_k;
    }
    __syncwarp();

    // fused std sums
    float s1 = 0.0f, s2 = 0.0f, z1 = 0.0f, z2 = 0.0f;
    {
        int fic = fi[gw];
        const float* fb = featsT + (size_t)b * N * C;
        const float* cfrow = fb + (size_t)fic * C;
        const int* sk = skout + warp * KNB;
        for (int c = lane; c < C; c += 32) {
            float cf = cfrow[c];
#pragma unroll 4
            for (int k = 0; k < KNB; k++) {
                float vv = fb[(size_t)sk[k] * C + c] - cf;
                s1 += vv; s2 = fmaf(vv, vv, s2);
            }
        }
    }
    if (lane < KNB) {
        float dx = spts[my_k * 3 + 0] - cx;
        float dy = spts[my_k * 3 + 1] - cy;
        float dz = spts[my_k * 3 + 2] - cz;
        z1 = dx + dy + dz;
        z2 = fmaf(dx, dx, fmaf(dy, dy, dz * dz));
    }
#pragma unroll
    for (int off = 16; off; off >>= 1) {
        s1 += __shfl_xor_sync(0xffffffffu, s1, off);
        s2 += __shfl_xor_sync(0xffffffffu, s2, off);
        z1 += __shfl_xor_sync(0xffffffffu, z1, off);
        z2 += __shfl_xor_sync(0xffffffffu, z2, off);
    }
    if (lane == 0) {
        atomicAdd(&sacc[0], s1); atomicAdd(&sacc[1], s2);
        atomicAdd(&sacc[2], z1); atomicAdd(&sacc[3], z2);
    }
    __syncthreads();
    if (tid == 0) {
        atomicAdd(&g_acc[0], (double)sacc[0]);
        atomicAdd(&g_acc[1], (double)sacc[1]);
        atomicAdd(&g_acc[2], (double)sacc[2]);
        atomicAdd(&g_acc[3], (double)sacc[3]);
    }
}

// ---------------- main LGA + mean-pool kernel ----------------
template<int CIN, int F>
__global__ void lga_kernel(const float* __restrict__ featsT, const float* __restrict__ pts,
                           const float* __restrict__ lc, const int* __restrict__ fi,
                           const int* __restrict__ ki, const float* __restrict__ Bmat,
                           const float* __restrict__ scl,
                           float* __restrict__ pooled, int G, int N,
                           double nx, double nz) {
    const int COUT = 2 * CIN, CHALF = CIN / 2, CPAIRS = CIN;
    __shared__ float sB[7 * CHALF];
    __shared__ float sde[F];
    __shared__ int   sidx[KNB];
    __shared__ float slc[3];
    __shared__ float sxyzn[KNB][3];
    __shared__ float sembin[KNB][7];
    __shared__ float spe[KNB + 1][COUT];
    __shared__ float s5[KNB][CIN];
    __shared__ float s_inv[2];

    int tid = threadIdx.x;
    int bg = blockIdx.x;
    int b  = bg / G;

    for (int i = tid; i < 7 * CHALF; i += blockDim.x) sB[i] = Bmat[i];
    if (tid < F)   sde[tid]  = scl[tid];
    if (tid < KNB) sidx[tid] = ki[(size_t)bg * KNB + tid];
    if (tid < 3)   slc[tid]  = lc[(size_t)bg * 3 + tid];
    if (tid == 0) {
        double vx = (g_acc[1] - g_acc[0] * g_acc[0] / nx) / (nx - 1.0);
        s_inv[0] = 1.0f / ((float)sqrt(vx) + 1e-5f);
        double vz = (g_acc[3] - g_acc[2] * g_acc[2] / nz) / (nz - 1.0);
        s_inv[1] = 1.0f / ((float)sqrt(vz) + 1e-5f);
    }
    __syncthreads();

    float invsx = s_inv[0], invsz = s_inv[1];

    if (tid < KNB * 3) {
        int k = tid / 3, c = tid - k * 3;
        float v = pts[((size_t)b * N + sidx[k]) * 3 + c];
        sxyzn[k][c] = (v - slc[c]) * invsz;
    }
    __syncthreads();

    if (tid < KNB) {
        float a0 = sxyzn[tid][0], a1 = sxyzn[tid][1], a2 = sxyzn[tid][2];
        float r0 = slc[0], r1 = slc[1], r2 = slc[2];
        sembin[tid][0] = a0; sembin[tid][1] = a1; sembin[tid][2] = a2;
        sembin[tid][3] = a1 * r2 - a2 * r1;
        sembin[tid][4] = a2 * r0 - a0 * r2;
        sembin[tid][5] = a0 * r1 - a1 * r0;
        sembin[tid][6] = a0 * r0 + a1 * r1 + a2 * r2;
    }

    // Phase A: unique pe sin/cos values
    {
        const int itemsA = CPAIRS * (KNB + 1);
        for (int it = tid; it < itemsA; it += blockDim.x) {
            int kk = it / CPAIRS;
            int p  = it - kk * CPAIRS;
            int comp = p / F, f = p - comp * F;
            float t = (kk < KNB) ? sxyzn[kk][comp] : slc[comp];
            float s, c;
            fsincos(t * sde[f], s, c);
            int m0 = comp * 2 * F + 2 * f;
            spe[kk][m0]     = s;
            spe[kk][m0 + 1] = c;
        }
    }
    __syncthreads();

    // Phase B: unique fourier projections -> sin^5, cos^5
    {
        const int itemsB = CHALF * KNB;
        for (int it = tid; it < itemsB; it += blockDim.x) {
            int kk = it / CHALF;
            int j  = it - kk * CHALF;
            float pr = 0.0f;
#pragma unroll
            for (int i = 0; i < 7; i++) pr += sembin[kk][i] * sB[i * CHALF + j];
            float ps, pc;
            fsincos(pr * 6.2831855f, ps, pc);
            float a  = ps * ps;
            float c2 = pc * pc;
            s5[kk][j]         = a * a * ps;
            s5[kk][j + CHALF] = c2 * c2 * pc;
        }
    }
    __syncthreads();

    // Phase C: accumulate over K
    int m = tid;
    float plc = spe[KNB][m];
    float acc = 0.0f;
    if (m < CIN) {
        const float* fbase = featsT + (size_t)b * N * CIN;
        float lcx = fbase[(size_t)fi[bg] * CIN + m];
#pragma unroll 4
        for (int k = 0; k < KNB; k++) {
            float pe  = spe[k][m] + plc;
            float val = (fbase[(size_t)sidx[k] * CIN + m] - lcx) * invsx;
            acc += (val + pe) * pe;
        }
    } else {
        int j = m - CIN;
#pragma unroll 4
        for (int k = 0; k < KNB; k++) {
            float pe = spe[k][m] + plc;
            acc += (s5[k][j] + pe) * pe;
        }
    }
    pooled[(size_t)bg * COUT + m] = acc * (2.0f / (float)KNB);
}

// ---------------- BN partial stats: coalesced (lane -> channel) ----------------
__global__ void bnstats_part(const float* __restrict__ pooled, int rows, int C2) {
    int tid = threadIdx.x;
    int repl = 576 / C2;
    int ch = tid % C2;
    int rr = tid / C2;
    int rpb = rows / gridDim.x;
    int r0 = blockIdx.x * rpb;
    float s1 = 0.0f, s2 = 0.0f;
    for (int r = r0 + rr; r < r0 + rpb; r += repl) {
        float v = pooled[(size_t)r * C2 + ch];
        s1 += v; s2 = fmaf(v, v, s2);
    }
    __shared__ float sh1[576], sh2[576];
    sh1[tid] = s1; sh2[tid] = s2;
    __syncthreads();
    if (rr == 0) {
        for (int j = 1; j < repl; j++) { s1 += sh1[tid + j * C2]; s2 += sh2[tid + j * C2]; }
        atomicAdd(&g_bnacc1[ch], (double)s1);
        atomicAdd(&g_bnacc2[ch], (double)s2);
    }
}

// ---------------- BN finalize ----------------
__global__ void bnfin(const float* __restrict__ gamma, const float* __restrict__ beta,
                      int rows, int C2) {
    int t = threadIdx.x;
    if (t < C2) {
        double mean = g_bnacc1[t] / rows;
        double var  = g_bnacc2[t] / rows - mean * mean;
        float rstd  = (float)(1.0 / sqrt(var + 1e-5));
        float sc    = gamma[t] * rstd;
        g_bnscale[t] = sc;
        g_bnshift[t] = beta[t] - (float)mean * sc;
        g_bnacc1[t] = 0.0; g_bnacc2[t] = 0.0;
    }
    if (t < 4) g_acc[t] = 0.0;
}

// ---------------- BN apply + exact GELU (row-major output, stage 1) ----------------
__global__ void bnapply_kernel(const float* __restrict__ pooled, float* __restrict__ outp,
                               int rows, int C2) {
    size_t n = (size_t)rows * C2;
    for (size_t i = (size_t)blockIdx.x * blockDim.x + threadIdx.x; i < n;
         i += (size_t)gridDim.x * blockDim.x) {
        int ch = (int)(i % C2);
        float y = pooled[i] * g_bnscale[ch] + g_bnshift[ch];
        outp[i] = 0.5f * y * (1.0f + erff(y * 0.70710678118654752440f));
    }
}

// ---------------- BN apply + GELU + tiled transpose (stage 2 output) ----------------
__global__ void bnapply_t(const float* __restrict__ pooled, float* __restrict__ outp) {
    __shared__ float t[32][33];
    int tx = threadIdx.x, ty = threadIdx.y;
    int ch = blockIdx.x * 32 + tx;
    int g0 = blockIdx.y * 32;
    int b  = blockIdx.z;
    float sc = g_bnscale[ch], sh = g_bnshift[ch];
#pragma unroll
    for (int j = 0; j < 4; j++) {
        int g = g0 + ty + j * 8;
        float y = pooled[((size_t)(b * G2 + g)) * C2OUT + ch] * sc + sh;
        t[ty + j * 8][tx] = 0.5f * y * (1.0f + erff(y * 0.70710678118654752440f));
    }
    __syncthreads();
#pragma unroll
    for (int j = 0; j < 4; j++) {
        int ch2 = blockIdx.x * 32 + ty + j * 8;
        outp[((size_t)(b * C2OUT + ch2)) * G2 + g0 + tx] = t[tx][ty + j * 8];
    }
}

// ---------------- side-stream infrastructure (created once at load) ----------------
struct SideStream {
    cudaStream_t s = 0;
    cudaEvent_t evA = 0, evT = 0, evF1 = 0, evB = 0;
    SideStream() {
        if (cudaStreamCreateWithFlags(&s, cudaStreamNonBlocking) != cudaSuccess) s = 0;
        cudaEventCreateWithFlags(&evA,  cudaEventDisableTiming);
        cudaEventCreateWithFlags(&evT,  cudaEventDisableTiming);
        cudaEventCreateWithFlags(&evF1, cudaEventDisableTiming);
        cudaEventCreateWithFlags(&evB,  cudaEventDisableTiming);
    }
};
static SideStream g_ss;

// ---------------- launch ----------------
extern "C" void kernel_launch(void* const* d_in, const int* in_sizes, int n_in,
                              void* d_out, int out_size) {
    (void)in_sizes; (void)n_in; (void)out_size;
    const float* xyz = (const float*)d_in[0];
    const float* x   = (const float*)d_in[1];
    const float* B0  = (const float*)d_in[2];
    const float* B1  = (const float*)d_in[3];
    const float* gm0 = (const float*)d_in[4];
    const float* bt0 = (const float*)d_in[5];
    const float* gm1 = (const float*)d_in[6];
    const float* bt1 = (const float*)d_in[7];
    float* out = (float*)d_out;

    float* featsT0 = nullptr; cudaGetSymbolAddress((void**)&featsT0, g_featsT0);
    int*   fi1 = nullptr;     cudaGetSymbolAddress((void**)&fi1, g_fi1);
    float* lc1 = nullptr;     cudaGetSymbolAddress((void**)&lc1, g_lc1);
    int*   ki1 = nullptr;     cudaGetSymbolAddress((void**)&ki1, g_ki1);
    float* pooled1 = nullptr; cudaGetSymbolAddress((void**)&pooled1, g_pooled1);
    float* featsT1 = nullptr; cudaGetSymbolAddress((void**)&featsT1, g_featsT1);
    int*   fi2 = nullptr;     cudaGetSymbolAddress((void**)&fi2, g_fi2);
    float* lc2 = nullptr;     cudaGetSymbolAddress((void**)&lc2, g_lc2);
    int*   ki2 = nullptr;     cudaGetSymbolAddress((void**)&ki2, g_ki2);
    float* pooled2 = nullptr; cudaGetSymbolAddress((void**)&pooled2, g_pooled2);
    float* sc1 = nullptr;     cudaGetSymbolAddress((void**)&sc1, g_sc1);
    float* sc2 = nullptr;     cudaGetSymbolAddress((void**)&sc2, g_sc2);

    const int SM1 = N0 * 3 * 4 + 16 * KNB * 4 + 16;   // 50704 B
    const int SM2 = G1 * 3 * 4 + 16 * KNB * 4 + 16;   // 26128 B
    cudaFuncSetAttribute(knn_std_kernel<N0, C0>,
                         cudaFuncAttributeMaxDynamicSharedMemorySize, SM1);
    cudaFuncSetAttribute(knn_std_kernel<G1, C1>,
                         cudaFuncAttributeMaxDynamicSharedMemorySize, SM2);
    const int FPSM1 = N0 * 3 * 4;                     // 49152 B
    const int FPSM2 = G1 * 3 * 4;                     // 24576 B
    cudaFuncSetAttribute(fps_kernel<4>,
                         cudaFuncAttributeMaxDynamicSharedMemorySize, FPSM1);
    cudaFuncSetAttribute(fps_kernel<2>,
                         cudaFuncAttributeMaxDynamicSharedMemorySize, FPSM2);

    cudaStream_t s2 = g_ss.s;
    bool fork = (s2 != 0);

    // Launch order (for ncu 4th-launch capture -> fps2):
    //   1 initk, 2 transpose_full(side), 3 fps1(main), 4 fps2(side)
    initk<<<1, 288>>>();
    if (fork) {
        cudaEventRecord(g_ss.evA, 0);
        cudaStreamWaitEvent(s2, g_ss.evA, 0);
        transpose_full<<<256, 256, 0, s2>>>(x, featsT0);
        cudaEventRecord(g_ss.evT, s2);
    } else {
        transpose_full<<<256, 256>>>(x, featsT0);
    }

    // ---------------- stage 1 ----------------
    fps_kernel<4><<<BATCH, 1024, FPSM1>>>(xyz, G1, fi1, lc1);       // main

    if (fork) {
        cudaEventRecord(g_ss.evF1, 0);
        cudaStreamWaitEvent(s2, g_ss.evF1, 0);
        fps_kernel<2><<<BATCH, 1024, FPSM2, s2>>>(lc1, G2, fi2, lc2); // side: overlap stage-1 tail
        cudaEventRecord(g_ss.evB, s2);
        cudaStreamWaitEvent(0, g_ss.evT, 0);      // knn1 needs featsT0
    }

    knn_std_kernel<N0, C0><<<BATCH * G1 / 16, 512, SM1>>>(xyz, lc1, featsT0, fi1, ki1, G1);
    lga_kernel<C0, 24><<<BATCH * G1, C1>>>(featsT0, xyz, lc1, fi1, ki1, B0, sc1, pooled1,
                                           G1, N0,
                                           (double)BATCH * G1 * KNB * C0,
                                           (double)BATCH * G1 * KNB * 3);
    bnstats_part<<<8, 576>>>(pooled1, BATCH * G1, C1);
    bnfin<<<1, 288>>>(gm0, bt0, BATCH * G1, C1);
    {
        size_t n = (size_t)BATCH * G1 * C1;
        bnapply_kernel<<<(int)((n + 255) / 256), 256>>>(pooled1, featsT1, BATCH * G1, C1);
    }

    // ---------------- stage 2 ----------------
    if (fork) {
        cudaStreamWaitEvent(0, g_ss.evB, 0);      // join fps2 before knn2
    } else {
        fps_kernel<2><<<BATCH, 1024, FPSM2>>>(lc1, G2, fi2, lc2);
    }
    knn_std_kernel<G1, C1><<<BATCH * G2 / 16, 512, SM2>>>(lc1, lc2, featsT1, fi2, ki2, G2);
    lga_kernel<C1, 48><<<BATCH * G2, C2OUT>>>(featsT1, lc1, lc2, fi2, ki2, B1, sc2, pooled2,
                                              G2, G1,
                                              (double)BATCH * G2 * KNB * C1,
                                              (double)BATCH * G2 * KNB * 3);
    bnstats_part<<<8, 576>>>(pooled2, BATCH * G2, C2OUT);
    bnfin<<<1, 288>>>(gm1, bt1, BATCH * G2, C2OUT);
    {
        dim3 grid(C2OUT / 32, G2 / 32, BATCH), block(32, 8);
        bnapply_t<<<grid, block>>>(pooled2, out);
    }
}

// round 17
// speedup vs baseline: 1.3945x; 1.3945x over previous
#include <cuda_runtime.h>
#include <math.h>
#include <float.h>

// Problem constants
#define BATCH 4
#define N0    4096
#define C0    72
#define G1    2048
#define C1    144
#define G2    1024
#define C2OUT 288
#define KNB   24

typedef unsigned long long u64;

// ---------------- scratch (static device globals; no allocation) ----------------
__device__ float  g_featsT0[BATCH * N0 * C0];
__device__ int    g_fi1[BATCH * G1];
__device__ float  g_lc1[BATCH * G1 * 3];
__device__ int    g_ki1[BATCH * G1 * KNB];
__device__ float  g_pooled1[BATCH * G1 * C1];
__device__ float  g_featsT1[BATCH * G1 * C1];
__device__ int    g_fi2[BATCH * G2];
__device__ float  g_lc2[BATCH * G2 * 3];
__device__ int    g_ki2[BATCH * G2 * KNB];
__device__ float  g_pooled2[BATCH * G2 * C2OUT];
__device__ double g_acc[4];                       // sumX, sumX2, sumZ, sumZ2
__device__ double g_bnacc1[C2OUT];
__device__ double g_bnacc2[C2OUT];
__device__ float  g_bnscale[C2OUT];
__device__ float  g_bnshift[C2OUT];
__device__ float  g_sc1[24];                      // stage1 1000/dim_embed
__device__ float  g_sc2[48];                      // stage2 1000/dim_embed

// ---------------- packed f32x2 helpers ----------------
__device__ __forceinline__ u64 pk2(float lo, float hi) {
    u64 r; asm("mov.b64 %0, {%1, %2};" : "=l"(r) : "f"(lo), "f"(hi)); return r;
}
__device__ __forceinline__ void upk2(u64 v, float& lo, float& hi) {
    asm("mov.b64 {%0, %1}, %2;" : "=f"(lo), "=f"(hi) : "l"(v));
}
__device__ __forceinline__ u64 add2(u64 a, u64 b) {
    u64 r; asm("add.rn.f32x2 %0, %1, %2;" : "=l"(r) : "l"(a), "l"(b)); return r;
}
__device__ __forceinline__ u64 mul2(u64 a, u64 b) {
    u64 r; asm("mul.rn.f32x2 %0, %1, %2;" : "=l"(r) : "l"(a), "l"(b)); return r;
}
__device__ __forceinline__ u64 fma2(u64 a, u64 b, u64 c) {
    u64 r; asm("fma.rn.f32x2 %0, %1, %2, %3;" : "=l"(r) : "l"(a), "l"(b), "l"(c)); return r;
}

// ---------------- fast sincos: Cody-Waite mod 2pi + MUFU ----------------
__device__ __forceinline__ void fsincos(float x, float& s, float& c) {
    float q = rintf(x * 0.15915494309189535f);
    float r = fmaf(q, -6.2831855f, x);
    r = fmaf(q, 1.7484556e-7f, r);
    __sincosf(r, &s, &c);
}

// ---------------- init: zero accumulators, build dim_embed tables ----------------
__global__ void initk() {
    int t = threadIdx.x;
    if (t < 4)  g_acc[t] = 0.0;
    if (t < 24) g_sc1[t] = (float)(1000.0 / pow(100.0, (double)t / 24.0));
    if (t < 48) g_sc2[t] = (float)(1000.0 / pow(100.0, (double)t / 48.0));
    for (int i = t; i < C2OUT; i += blockDim.x) { g_bnacc1[i] = 0.0; g_bnacc2[i] = 0.0; }
}

// ---------------- transpose [B][C][N] -> [B][N][C] (single launch) ----------------
__global__ void transpose_full(const float* __restrict__ x, float* __restrict__ o) {
    size_t tot = (size_t)BATCH * C0 * N0;
    for (size_t i = (size_t)blockIdx.x * blockDim.x + threadIdx.x; i < tot;
         i += (size_t)gridDim.x * blockDim.x) {
        size_t b   = i / ((size_t)C0 * N0);
        size_t rem = i - b * (size_t)C0 * N0;
        size_t c   = rem / N0;
        size_t n   = rem - c * N0;
        o[(b * N0 + n) * C0 + c] = x[i];
    }
}

// ---------------- furthest point sampling ----------------
// One block per batch, 1024 threads, PPT contiguous points per thread.
// Chain-optimized: ALL lanes compute their candidate's argmax position and
// coords FROM REGISTERS (overlapping the redux/ballot latency); the winner
// lane publishes dist (STS.32) + float4{x,y,z,idx} (STS.128). No smem point
// tile, no dependent LDS before the barrier. Tie rule (lowest-j, lowest-lane,
// lowest-warp = global first-max) preserved; distance arithmetic unchanged.
template<int PPT>
__global__ void __launch_bounds__(1024) fps_kernel(const float* __restrict__ pts,
                                                   int m,
                                                   int* __restrict__ fi,
                                                   float* __restrict__ lc) {
    const int T = 1024;
    const int P2 = PPT / 2;
    __shared__ float  swd[2][32];
    __shared__ float4 swf[2][32];
    int b = blockIdx.x;
    const float* P = pts + (size_t)b * (T * PPT) * 3;
    int tid = threadIdx.x, lane = tid & 31, warp = tid >> 5;
    int base = tid * PPT;

    u64 X[P2], Y[P2], Z[P2];
    float dist[PPT];
#pragma unroll
    for (int j = 0; j < P2; j++) {
        int n0 = (base + 2 * j) * 3;
        X[j] = pk2(P[n0 + 0], P[n0 + 3]);
        Y[j] = pk2(P[n0 + 1], P[n0 + 4]);
        Z[j] = pk2(P[n0 + 2], P[n0 + 5]);
        dist[2 * j] = 1e10f; dist[2 * j + 1] = 1e10f;
    }

    float cx = P[0], cy = P[1], cz = P[2];       // initial centroid = point 0
    unsigned curidx = 0;
    int buf = 0;

    for (int it = 0; it < m; it++) {
        if (tid == 0) {
            fi[b * m + it] = (int)curidx;
            lc[(size_t)(b * m + it) * 3 + 0] = cx;
            lc[(size_t)(b * m + it) * 3 + 1] = cy;
            lc[(size_t)(b * m + it) * 3 + 2] = cz;
        }
        u64 mcx = pk2(-cx, -cx), mcy = pk2(-cy, -cy), mcz = pk2(-cz, -cz);
        float mx0 = -1.0f, mx1 = -1.0f;
#pragma unroll
        for (int j = 0; j < P2; j++) {
            u64 dx = add2(X[j], mcx);
            u64 dy = add2(Y[j], mcy);
            u64 dz = add2(Z[j], mcz);
            u64 t  = mul2(dz, dz);
            t = fma2(dy, dy, t);
            t = fma2(dx, dx, t);               // == fmaf(dx,dx,fmaf(dy,dy,dz*dz)) per half
            float t0, t1; upk2(t, t0, t1);
            float nd0 = fminf(dist[2 * j],     t0);
            float nd1 = fminf(dist[2 * j + 1], t1);
            dist[2 * j] = nd0;
            dist[2 * j + 1] = nd1;
            mx0 = fmaxf(mx0, nd0);
            mx1 = fmaxf(mx1, nd1);
        }
        float mx = fmaxf(mx0, mx1);
        unsigned dbits = __float_as_uint(mx);            // >=0 -> monotone as uint
        unsigned md  = __reduce_max_sync(0xffffffffu, dbits);
        unsigned bal = __ballot_sync(0xffffffffu, dbits == md);
        int src = __ffs(bal) - 1;                        // lowest lane = lowest index

        // ALL lanes: locate candidate + extract its coords from registers.
        // Independent of redux/ballot above -> overlaps their latency.
        int loc = 0;
#pragma unroll
        for (int j = PPT - 1; j >= 0; j--)               // smallest j with dist==mx
            if (dist[j] == mx) loc = j;
        int pj = loc >> 1, ph = loc & 1;
        u64 ux = X[0], uy = Y[0], uz = Z[0];
#pragma unroll
        for (int jj = 1; jj < P2; jj++)
            if (pj == jj) { ux = X[jj]; uy = Y[jj]; uz = Z[jj]; }
        float x0, x1, y0, y1, z0, z1;
        upk2(ux, x0, x1); upk2(uy, y0, y1); upk2(uz, z0, z1);
        float pxx = ph ? x1 : x0;
        float pyy = ph ? y1 : y0;
        float pzz = ph ? z1 : z0;

        if (lane == src) {
            swd[buf][warp] = mx;
            swf[buf][warp] = make_float4(pxx, pyy, pzz,
                                         __uint_as_float((unsigned)(base + loc)));
        }
        __syncthreads();
        unsigned d2 = __float_as_uint(swd[buf][lane]);   // 32 warps -> all lanes valid
        unsigned md2  = __reduce_max_sync(0xffffffffu, d2);
        unsigned bal2 = __ballot_sync(0xffffffffu, d2 == md2);
        int wsrc = __ffs(bal2) - 1;                      // lowest warp = lowest index
        float4 w = swf[buf][wsrc];                       // one broadcast LDS.128
        cx = w.x; cy = w.y; cz = w.z;
        curidx = __float_as_uint(w.w);
        buf ^= 1;
    }
}

// ---------------- kNN (smem tile, two-pass threshold) + fused global-std ----------------
template<int N, int C>
__global__ void __launch_bounds__(512) knn_std_kernel(
    const float* __restrict__ pts, const float* __restrict__ ctr,
    const float* __restrict__ featsT, const int* __restrict__ fi,
    int* __restrict__ ki, int G)
{
    extern __shared__ float dynsmem[];
    float* spts = dynsmem;                       // N*3 floats
    int*   skout = (int*)(dynsmem + N * 3);      // 16*KNB ints
    float* sacc  = (float*)(skout + 16 * KNB);   // 4 floats

    int tid = threadIdx.x, lane = tid & 31, warp = tid >> 5;
    int gw = blockIdx.x * 16 + warp;
    int b = gw / G;                              // block-uniform (G % 16 == 0)
    const float* P = pts + (size_t)b * N * 3;

    {   // coalesced tile load
        const float4* P4 = (const float4*)P;
        float4* S4 = (float4*)spts;
        for (int i = tid; i < N * 3 / 4; i += 512) S4[i] = P4[i];
    }
    if (tid < 4) sacc[tid] = 0.0f;
    __syncthreads();

    float cx = ctr[(size_t)gw * 3 + 0];
    float cy = ctr[(size_t)gw * 3 + 1];
    float cz = ctr[(size_t)gw * 3 + 2];

    // ---- pass 1: per-lane min -> tau bound ----
    float mn = FLT_MAX;
    for (int n = lane; n < N; n += 32) {
        float dx = spts[n * 3 + 0] - cx;
        float dy = spts[n * 3 + 1] - cy;
        float dz = spts[n * 3 + 2] - cz;
        mn = fminf(mn, fmaf(dx, dx, fmaf(dy, dy, dz * dz)));
    }
    float v = mn;
#pragma unroll
    for (int k = 2; k <= 32; k <<= 1) {
#pragma unroll
        for (int j = k >> 1; j > 0; j >>= 1) {
            float o = __shfl_xor_sync(0xffffffffu, v, j);
            bool dirUp   = ((lane & k) == 0);
            bool takeLow = ((lane & j) == 0);
            v = (dirUp == takeLow) ? fminf(v, o) : fmaxf(v, o);
        }
    }
    float tau = __shfl_sync(0xffffffffu, v, KNB - 1);   // 24th smallest lane-min

    // ---- pass 2: thresholded insertion ----
    float kd[KNB]; int kix[KNB];
#pragma unroll
    for (int i = 0; i < KNB; i++) { kd[i] = FLT_MAX; kix[i] = 0x7fffffff; }
    float wd = FLT_MAX; int wi = 0x7fffffff;

    for (int n = lane; n < N; n += 32) {
        float dx = spts[n * 3 + 0] - cx;
        float dy = spts[n * 3 + 1] - cy;
        float dz = spts[n * 3 + 2] - cz;
        float d  = fmaf(dx, dx, fmaf(dy, dy, dz * dz));
        if (d > tau) continue;                   // cannot be in global top-24
        if (d < wd || (d == wd && n < wi)) {
            int i = KNB - 1;
            while (i > 0 && (kd[i - 1] > d || (kd[i - 1] == d && kix[i - 1] > n))) {
                kd[i] = kd[i - 1]; kix[i] = kix[i - 1]; i--;
            }
            kd[i] = d; kix[i] = n;
            wd = kd[KNB - 1]; wi = kix[KNB - 1];
        }
    }

    // warp merge: 24 rounds of lexicographic min extraction
    int my_k = 0;
    int pos = 0;
    for (int r = 0; r < KNB; r++) {
        float vv = (pos < KNB) ? kd[pos]  : FLT_MAX;
        int   id = (pos < KNB) ? kix[pos] : 0x7fffffff;
        float bv = vv; int bi = id;
#pragma unroll
        for (int off = 16; off; off >>= 1) {
            float ov = __shfl_xor_sync(0xffffffffu, bv, off);
            int   oi = __shfl_xor_sync(0xffffffffu, bi, off);
            if (ov < bv || (ov == bv && oi < bi)) { bv = ov; bi = oi; }
        }
        if (id == bi && vv == bv) pos++;
        if (lane == r) my_k = bi;
    }
    if (lane < KNB) {
        ki[(size_t)gw * KNB + lane] = my_k;
        skout[warp * KNB + lane] = my_k;
    }
    __syncwarp();

    // fused std sums
    float s1 = 0.0f, s2 = 0.0f, z1 = 0.0f, z2 = 0.0f;
    {
        int fic = fi[gw];
        const float* fb = featsT + (size_t)b * N * C;
        const float* cfrow = fb + (size_t)fic * C;
        const int* sk = skout + warp * KNB;
        for (int c = lane; c < C; c += 32) {
            float cf = cfrow[c];
#pragma unroll 4
            for (int k = 0; k < KNB; k++) {
                float vv = fb[(size_t)sk[k] * C + c] - cf;
                s1 += vv; s2 = fmaf(vv, vv, s2);
            }
        }
    }
    if (lane < KNB) {
        float dx = spts[my_k * 3 + 0] - cx;
        float dy = spts[my_k * 3 + 1] - cy;
        float dz = spts[my_k * 3 + 2] - cz;
        z1 = dx + dy + dz;
        z2 = fmaf(dx, dx, fmaf(dy, dy, dz * dz));
    }
#pragma unroll
    for (int off = 16; off; off >>= 1) {
        s1 += __shfl_xor_sync(0xffffffffu, s1, off);
        s2 += __shfl_xor_sync(0xffffffffu, s2, off);
        z1 += __shfl_xor_sync(0xffffffffu, z1, off);
        z2 += __shfl_xor_sync(0xffffffffu, z2, off);
    }
    if (lane == 0) {
        atomicAdd(&sacc[0], s1); atomicAdd(&sacc[1], s2);
        atomicAdd(&sacc[2], z1); atomicAdd(&sacc[3], z2);
    }
    __syncthreads();
    if (tid == 0) {
        atomicAdd(&g_acc[0], (double)sacc[0]);
        atomicAdd(&g_acc[1], (double)sacc[1]);
        atomicAdd(&g_acc[2], (double)sacc[2]);
        atomicAdd(&g_acc[3], (double)sacc[3]);
    }
}

// ---------------- main LGA + mean-pool kernel ----------------
template<int CIN, int F>
__global__ void lga_kernel(const float* __restrict__ featsT, const float* __restrict__ pts,
                           const float* __restrict__ lc, const int* __restrict__ fi,
                           const int* __restrict__ ki, const float* __restrict__ Bmat,
                           const float* __restrict__ scl,
                           float* __restrict__ pooled, int G, int N,
                           double nx, double nz) {
    const int COUT = 2 * CIN, CHALF = CIN / 2, CPAIRS = CIN;
    __shared__ float sB[7 * CHALF];
    __shared__ float sde[F];
    __shared__ int   sidx[KNB];
    __shared__ float slc[3];
    __shared__ float sxyzn[KNB][3];
    __shared__ float sembin[KNB][7];
    __shared__ float spe[KNB + 1][COUT];
    __shared__ float s5[KNB][CIN];
    __shared__ float s_inv[2];

    int tid = threadIdx.x;
    int bg = blockIdx.x;
    int b  = bg / G;

    for (int i = tid; i < 7 * CHALF; i += blockDim.x) sB[i] = Bmat[i];
    if (tid < F)   sde[tid]  = scl[tid];
    if (tid < KNB) sidx[tid] = ki[(size_t)bg * KNB + tid];
    if (tid < 3)   slc[tid]  = lc[(size_t)bg * 3 + tid];
    if (tid == 0) {
        double vx = (g_acc[1] - g_acc[0] * g_acc[0] / nx) / (nx - 1.0);
        s_inv[0] = 1.0f / ((float)sqrt(vx) + 1e-5f);
        double vz = (g_acc[3] - g_acc[2] * g_acc[2] / nz) / (nz - 1.0);
        s_inv[1] = 1.0f / ((float)sqrt(vz) + 1e-5f);
    }
    __syncthreads();

    float invsx = s_inv[0], invsz = s_inv[1];

    if (tid < KNB * 3) {
        int k = tid / 3, c = tid - k * 3;
        float v = pts[((size_t)b * N + sidx[k]) * 3 + c];
        sxyzn[k][c] = (v - slc[c]) * invsz;
    }
    __syncthreads();

    if (tid < KNB) {
        float a0 = sxyzn[tid][0], a1 = sxyzn[tid][1], a2 = sxyzn[tid][2];
        float r0 = slc[0], r1 = slc[1], r2 = slc[2];
        sembin[tid][0] = a0; sembin[tid][1] = a1; sembin[tid][2] = a2;
        sembin[tid][3] = a1 * r2 - a2 * r1;
        sembin[tid][4] = a2 * r0 - a0 * r2;
        sembin[tid][5] = a0 * r1 - a1 * r0;
        sembin[tid][6] = a0 * r0 + a1 * r1 + a2 * r2;
    }

    // Phase A: unique pe sin/cos values
    {
        const int itemsA = CPAIRS * (KNB + 1);
        for (int it = tid; it < itemsA; it += blockDim.x) {
            int kk = it / CPAIRS;
            int p  = it - kk * CPAIRS;
            int comp = p / F, f = p - comp * F;
            float t = (kk < KNB) ? sxyzn[kk][comp] : slc[comp];
            float s, c;
            fsincos(t * sde[f], s, c);
            int m0 = comp * 2 * F + 2 * f;
            spe[kk][m0]     = s;
            spe[kk][m0 + 1] = c;
        }
    }
    __syncthreads();

    // Phase B: unique fourier projections -> sin^5, cos^5
    {
        const int itemsB = CHALF * KNB;
        for (int it = tid; it < itemsB; it += blockDim.x) {
            int kk = it / CHALF;
            int j  = it - kk * CHALF;
            float pr = 0.0f;
#pragma unroll
            for (int i = 0; i < 7; i++) pr += sembin[kk][i] * sB[i * CHALF + j];
            float ps, pc;
            fsincos(pr * 6.2831855f, ps, pc);
            float a  = ps * ps;
            float c2 = pc * pc;
            s5[kk][j]         = a * a * ps;
            s5[kk][j + CHALF] = c2 * c2 * pc;
        }
    }
    __syncthreads();

    // Phase C: accumulate over K
    int m = tid;
    float plc = spe[KNB][m];
    float acc = 0.0f;
    if (m < CIN) {
        const float* fbase = featsT + (size_t)b * N * CIN;
        float lcx = fbase[(size_t)fi[bg] * CIN + m];
#pragma unroll 4
        for (int k = 0; k < KNB; k++) {
            float pe  = spe[k][m] + plc;
            float val = (fbase[(size_t)sidx[k] * CIN + m] - lcx) * invsx;
            acc += (val + pe) * pe;
        }
    } else {
        int j = m - CIN;
#pragma unroll 4
        for (int k = 0; k < KNB; k++) {
            float pe = spe[k][m] + plc;
            acc += (s5[k][j] + pe) * pe;
        }
    }
    pooled[(size_t)bg * COUT + m] = acc * (2.0f / (float)KNB);
}

// ---------------- BN partial stats: coalesced (lane -> channel) ----------------
__global__ void bnstats_part(const float* __restrict__ pooled, int rows, int C2) {
    int tid = threadIdx.x;
    int repl = 576 / C2;
    int ch = tid % C2;
    int rr = tid / C2;
    int rpb = rows / gridDim.x;
    int r0 = blockIdx.x * rpb;
    float s1 = 0.0f, s2 = 0.0f;
    for (int r = r0 + rr; r < r0 + rpb; r += repl) {
        float v = pooled[(size_t)r * C2 + ch];
        s1 += v; s2 = fmaf(v, v, s2);
    }
    __shared__ float sh1[576], sh2[576];
    sh1[tid] = s1; sh2[tid] = s2;
    __syncthreads();
    if (rr == 0) {
        for (int j = 1; j < repl; j++) { s1 += sh1[tid + j * C2]; s2 += sh2[tid + j * C2]; }
        atomicAdd(&g_bnacc1[ch], (double)s1);
        atomicAdd(&g_bnacc2[ch], (double)s2);
    }
}

// ---------------- BN finalize ----------------
__global__ void bnfin(const float* __restrict__ gamma, const float* __restrict__ beta,
                      int rows, int C2) {
    int t = threadIdx.x;
    if (t < C2) {
        double mean = g_bnacc1[t] / rows;
        double var  = g_bnacc2[t] / rows - mean * mean;
        float rstd  = (float)(1.0 / sqrt(var + 1e-5));
        float sc    = gamma[t] * rstd;
        g_bnscale[t] = sc;
        g_bnshift[t] = beta[t] - (float)mean * sc;
        g_bnacc1[t] = 0.0; g_bnacc2[t] = 0.0;
    }
    if (t < 4) g_acc[t] = 0.0;
}

// ---------------- BN apply + exact GELU (row-major output, stage 1) ----------------
__global__ void bnapply_kernel(const float* __restrict__ pooled, float* __restrict__ outp,
                               int rows, int C2) {
    size_t n = (size_t)rows * C2;
    for (size_t i = (size_t)blockIdx.x * blockDim.x + threadIdx.x; i < n;
         i += (size_t)gridDim.x * blockDim.x) {
        int ch = (int)(i % C2);
        float y = pooled[i] * g_bnscale[ch] + g_bnshift[ch];
        outp[i] = 0.5f * y * (1.0f + erff(y * 0.70710678118654752440f));
    }
}

// ---------------- BN apply + GELU + tiled transpose (stage 2 output) ----------------
__global__ void bnapply_t(const float* __restrict__ pooled, float* __restrict__ outp) {
    __shared__ float t[32][33];
    int tx = threadIdx.x, ty = threadIdx.y;
    int ch = blockIdx.x * 32 + tx;
    int g0 = blockIdx.y * 32;
    int b  = blockIdx.z;
    float sc = g_bnscale[ch], sh = g_bnshift[ch];
#pragma unroll
    for (int j = 0; j < 4; j++) {
        int g = g0 + ty + j * 8;
        float y = pooled[((size_t)(b * G2 + g)) * C2OUT + ch] * sc + sh;
        t[ty + j * 8][tx] = 0.5f * y * (1.0f + erff(y * 0.70710678118654752440f));
    }
    __syncthreads();
#pragma unroll
    for (int j = 0; j < 4; j++) {
        int ch2 = blockIdx.x * 32 + ty + j * 8;
        outp[((size_t)(b * C2OUT + ch2)) * G2 + g0 + tx] = t[tx][ty + j * 8];
    }
}

// ---------------- side-stream infrastructure (created once at load) ----------------
struct SideStream {
    cudaStream_t s = 0;
    cudaEvent_t evA = 0, evT = 0, evF1 = 0, evB = 0;
    SideStream() {
        if (cudaStreamCreateWithFlags(&s, cudaStreamNonBlocking) != cudaSuccess) s = 0;
        cudaEventCreateWithFlags(&evA,  cudaEventDisableTiming);
        cudaEventCreateWithFlags(&evT,  cudaEventDisableTiming);
        cudaEventCreateWithFlags(&evF1, cudaEventDisableTiming);
        cudaEventCreateWithFlags(&evB,  cudaEventDisableTiming);
    }
};
static SideStream g_ss;

// ---------------- launch ----------------
extern "C" void kernel_launch(void* const* d_in, const int* in_sizes, int n_in,
                              void* d_out, int out_size) {
    (void)in_sizes; (void)n_in; (void)out_size;
    const float* xyz = (const float*)d_in[0];
    const float* x   = (const float*)d_in[1];
    const float* B0  = (const float*)d_in[2];
    const float* B1  = (const float*)d_in[3];
    const float* gm0 = (const float*)d_in[4];
    const float* bt0 = (const float*)d_in[5];
    const float* gm1 = (const float*)d_in[6];
    const float* bt1 = (const float*)d_in[7];
    float* out = (float*)d_out;

    float* featsT0 = nullptr; cudaGetSymbolAddress((void**)&featsT0, g_featsT0);
    int*   fi1 = nullptr;     cudaGetSymbolAddress((void**)&fi1, g_fi1);
    float* lc1 = nullptr;     cudaGetSymbolAddress((void**)&lc1, g_lc1);
    int*   ki1 = nullptr;     cudaGetSymbolAddress((void**)&ki1, g_ki1);
    float* pooled1 = nullptr; cudaGetSymbolAddress((void**)&pooled1, g_pooled1);
    float* featsT1 = nullptr; cudaGetSymbolAddress((void**)&featsT1, g_featsT1);
    int*   fi2 = nullptr;     cudaGetSymbolAddress((void**)&fi2, g_fi2);
    float* lc2 = nullptr;     cudaGetSymbolAddress((void**)&lc2, g_lc2);
    int*   ki2 = nullptr;     cudaGetSymbolAddress((void**)&ki2, g_ki2);
    float* pooled2 = nullptr; cudaGetSymbolAddress((void**)&pooled2, g_pooled2);
    float* sc1 = nullptr;     cudaGetSymbolAddress((void**)&sc1, g_sc1);
    float* sc2 = nullptr;     cudaGetSymbolAddress((void**)&sc2, g_sc2);

    const int SM1 = N0 * 3 * 4 + 16 * KNB * 4 + 16;   // 50704 B
    const int SM2 = G1 * 3 * 4 + 16 * KNB * 4 + 16;   // 26128 B
    cudaFuncSetAttribute(knn_std_kernel<N0, C0>,
                         cudaFuncAttributeMaxDynamicSharedMemorySize, SM1);
    cudaFuncSetAttribute(knn_std_kernel<G1, C1>,
                         cudaFuncAttributeMaxDynamicSharedMemorySize, SM2);

    cudaStream_t s2 = g_ss.s;
    bool fork = (s2 != 0);

    // Launch order (ncu 4th-launch capture -> fps2):
    //   1 initk, 2 transpose_full(side), 3 fps1(main), 4 fps2(side)
    initk<<<1, 288>>>();
    if (fork) {
        cudaEventRecord(g_ss.evA, 0);
        cudaStreamWaitEvent(s2, g_ss.evA, 0);
        transpose_full<<<256, 256, 0, s2>>>(x, featsT0);
        cudaEventRecord(g_ss.evT, s2);
    } else {
        transpose_full<<<256, 256>>>(x, featsT0);
    }

    // ---------------- stage 1 ----------------
    fps_kernel<4><<<BATCH, 1024>>>(xyz, G1, fi1, lc1);              // main

    if (fork) {
        cudaEventRecord(g_ss.evF1, 0);
        cudaStreamWaitEvent(s2, g_ss.evF1, 0);
        fps_kernel<2><<<BATCH, 1024, 0, s2>>>(lc1, G2, fi2, lc2);   // side: overlap stage-1 tail
        cudaEventRecord(g_ss.evB, s2);
        cudaStreamWaitEvent(0, g_ss.evT, 0);      // knn1 needs featsT0
    }

    knn_std_kernel<N0, C0><<<BATCH * G1 / 16, 512, SM1>>>(xyz, lc1, featsT0, fi1, ki1, G1);
    lga_kernel<C0, 24><<<BATCH * G1, C1>>>(featsT0, xyz, lc1, fi1, ki1, B0, sc1, pooled1,
                                           G1, N0,
                                           (double)BATCH * G1 * KNB * C0,
                                           (double)BATCH * G1 * KNB * 3);
    bnstats_part<<<8, 576>>>(pooled1, BATCH * G1, C1);
    bnfin<<<1, 288>>>(gm0, bt0, BATCH * G1, C1);
    {
        size_t n = (size_t)BATCH * G1 * C1;
        bnapply_kernel<<<(int)((n + 255) / 256), 256>>>(pooled1, featsT1, BATCH * G1, C1);
    }

    // ---------------- stage 2 ----------------
    if (fork) {
        cudaStreamWaitEvent(0, g_ss.evB, 0);      // join fps2 before knn2
    } else {
        fps_kernel<2><<<BATCH, 1024>>>(lc1, G2, fi2, lc2);
    }
    knn_std_kernel<G1, C1><<<BATCH * G2 / 16, 512, SM2>>>(lc1, lc2, featsT1, fi2, ki2, G2);
    lga_kernel<C1, 48><<<BATCH * G2, C2OUT>>>(featsT1, lc1, lc2, fi2, ki2, B1, sc2, pooled2,
                                              G2, G1,
                                              (double)BATCH * G2 * KNB * C1,
                                              (double)BATCH * G2 * KNB * 3);
    bnstats_part<<<8, 576>>>(pooled2, BATCH * G2, C2OUT);
    bnfin<<<1, 288>>>(gm1, bt1, BATCH * G2, C2OUT);
    {
        dim3 grid(C2OUT / 32, G2 / 32, BATCH), block(32, 8);
        bnapply_t<<<grid, block>>>(pooled2, out);
    }
}